// round 5
// baseline (speedup 1.0000x reference)
#include <cuda_runtime.h>
#include <math.h>
#include <stdint.h>
#include <stddef.h>

#define N0V 50000
#define N1V 150000
#define N2V 100000
#define DV  256

// ---- scratch (device globals: no allocation allowed) ----
__device__ float g_xj0[(size_t)N0V * DV];
__device__ float g_xj1[(size_t)N1V * DV];
__device__ float g_xj2[(size_t)N2V * DV];
__device__ float g_ai0[N0V];
__device__ float g_aj0[N0V];
__device__ float g_aj1[N1V];
__device__ float g_aj2[N2V];

__device__ __forceinline__ void cp16(uint32_t dst, const void* src, bool valid)
{
    const int sz = valid ? 16 : 0;
    asm volatile("cp.async.cg.shared.global [%0], [%1], 16, %2;"
                 :: "r"(dst), "l"(src), "r"(sz));
}

// ============================================================
// Tensor-core GEMM: Y[M,256] = relu(X[M,256] @ W[256,256]^T + b)
// Fused: avec[row] += Y[row,:] . aw + ab
//
// Block 128x256 (full N), 512 threads = 16 warps of 64x32.
// BK=32, 3-stage cp.async pipeline. Raw fp32 bits fed to
// mma.tf32 (hardware truncation; no per-fragment cvt).
// XOR-swizzled 16B chunks; shared k-permutation for A and B.
// ============================================================
#define BM 128
#define BK 32
#define NSTAGE 3
#define A_BYTES (BM * BK * 4)          // 16 KB
#define B_BYTES (256 * BK * 4)         // 32 KB
#define STAGE_BYTES (A_BYTES + B_BYTES)
#define SMEM_BYTES (NSTAGE * STAGE_BYTES)   // 144 KB

__global__ __launch_bounds__(512, 1)
void gemm_tf32_kernel(const float* __restrict__ X,
                      const float* __restrict__ W,
                      const float* __restrict__ bias,
                      const float* __restrict__ aw,
                      const float* __restrict__ ab,
                      float* __restrict__ Y,
                      float* __restrict__ avec,
                      int M)
{
    extern __shared__ char smem[];
    const uint32_t smem_u32 = (uint32_t)__cvta_generic_to_shared(smem);

    const int t    = threadIdx.x;
    const int wid  = t >> 5;
    const int lane = t & 31;
    const int grp  = lane >> 2;   // 0..7
    const int tig  = lane & 3;    // 0..3
    const int warp_m = wid & 1;   // 64-row half
    const int warp_n = wid >> 1;  // 0..7 -> 32 cols each
    const int bm = blockIdx.x * BM;

    float acc[4][4][4];
#pragma unroll
    for (int mi = 0; mi < 4; mi++)
#pragma unroll
        for (int nj = 0; nj < 4; nj++)
#pragma unroll
            for (int r = 0; r < 4; r++) acc[mi][nj][r] = 0.0f;

    // ---- async tile loader (A: 1024 16B chunks, B: 2048) ----
    auto load_stage = [&](int kt, int stage) {
        const uint32_t abase = smem_u32 + stage * STAGE_BYTES;
        const uint32_t bbase = abase + A_BYTES;
#pragma unroll
        for (int l = 0; l < 2; l++) {
            const int i   = t + l * 512;
            const int row = i >> 3;
            const int c   = i & 7;
            const uint32_t dst = abase + row * 128 + ((c ^ (row & 7)) << 4);
            const float* src = X + (size_t)(bm + row) * DV + kt * BK + c * 4;
            cp16(dst, src, (bm + row) < M);
        }
#pragma unroll
        for (int l = 0; l < 4; l++) {
            const int i   = t + l * 512;
            const int col = i >> 3;
            const int c   = i & 7;
            const uint32_t dst = bbase + col * 128 + ((c ^ (col & 7)) << 4);
            const float* src = W + (size_t)col * DV + kt * BK + c * 4;
            cp16(dst, src, true);
        }
        asm volatile("cp.async.commit_group;");
    };

    const int NKT = DV / BK;  // 8
    load_stage(0, 0);
    load_stage(1, 1);

    int stage = 0;
    for (int kt = 0; kt < NKT; kt++) {
        if (kt + 2 < NKT) {
            load_stage(kt + 2, (kt + 2) % NSTAGE);
            asm volatile("cp.async.wait_group 2;");
        } else if (kt + 1 < NKT) {
            asm volatile("cp.async.wait_group 1;");
        } else {
            asm volatile("cp.async.wait_group 0;");
        }
        __syncthreads();

        const char* abase = smem + stage * STAGE_BYTES;
        const char* bbase = abase + A_BYTES;
        stage = (stage + 1 == NSTAGE) ? 0 : stage + 1;

#pragma unroll
        for (int half = 0; half < 2; half++) {
            const int chunk = ((2 * tig + half) ^ grp) << 4;
            uint32_t a[4][2][4];
#pragma unroll
            for (int mi = 0; mi < 4; mi++)
#pragma unroll
                for (int rh = 0; rh < 2; rh++) {
                    const int r = warp_m * 64 + mi * 16 + rh * 8 + grp;
                    const uint4 v = *(const uint4*)(abase + r * 128 + chunk);
                    a[mi][rh][0] = v.x; a[mi][rh][1] = v.y;
                    a[mi][rh][2] = v.z; a[mi][rh][3] = v.w;
                }
            uint32_t b[4][4];
#pragma unroll
            for (int nj = 0; nj < 4; nj++) {
                const int c = warp_n * 32 + nj * 8 + grp;
                const uint4 v = *(const uint4*)(bbase + c * 128 + chunk);
                b[nj][0] = v.x; b[nj][1] = v.y;
                b[nj][2] = v.z; b[nj][3] = v.w;
            }
#pragma unroll
            for (int s2 = 0; s2 < 2; s2++)
#pragma unroll
                for (int mi = 0; mi < 4; mi++)
#pragma unroll
                    for (int nj = 0; nj < 4; nj++) {
                        asm volatile(
                            "mma.sync.aligned.m16n8k8.row.col.f32.tf32.tf32.f32 "
                            "{%0,%1,%2,%3}, {%4,%5,%6,%7}, {%8,%9}, {%0,%1,%2,%3};"
                            : "+f"(acc[mi][nj][0]), "+f"(acc[mi][nj][1]),
                              "+f"(acc[mi][nj][2]), "+f"(acc[mi][nj][3])
                            : "r"(a[mi][0][2 * s2]), "r"(a[mi][1][2 * s2]),
                              "r"(a[mi][0][2 * s2 + 1]), "r"(a[mi][1][2 * s2 + 1]),
                              "r"(b[nj][2 * s2]), "r"(b[nj][2 * s2 + 1]));
                    }
        }
        __syncthreads();
    }

    // ---- epilogue: +bias, relu, store, fused attention dot ----
    float awv[4][2], bv[4][2];
#pragma unroll
    for (int nj = 0; nj < 4; nj++) {
        const int col = warp_n * 32 + nj * 8 + 2 * tig;
        const float2 a2 = *(const float2*)(aw + col);
        const float2 b2 = *(const float2*)(bias + col);
        awv[nj][0] = a2.x; awv[nj][1] = a2.y;
        bv[nj][0]  = b2.x; bv[nj][1]  = b2.y;
    }
    const float abv = __ldg(ab);
    const bool add_ab = (warp_n == 0);

#pragma unroll
    for (int mi = 0; mi < 4; mi++) {
#pragma unroll
        for (int h = 0; h < 2; h++) {
            const int gr = bm + warp_m * 64 + mi * 16 + grp + h * 8;
            float dp = 0.0f;
            float2 st[4];
#pragma unroll
            for (int nj = 0; nj < 4; nj++) {
                const float v0 = fmaxf(acc[mi][nj][h * 2 + 0] + bv[nj][0], 0.f);
                const float v1 = fmaxf(acc[mi][nj][h * 2 + 1] + bv[nj][1], 0.f);
                dp += v0 * awv[nj][0] + v1 * awv[nj][1];
                st[nj].x = v0; st[nj].y = v1;
            }
            dp += __shfl_xor_sync(0xffffffffu, dp, 1);
            dp += __shfl_xor_sync(0xffffffffu, dp, 2);
            if (gr < M) {
#pragma unroll
                for (int nj = 0; nj < 4; nj++) {
                    const int col = warp_n * 32 + nj * 8 + 2 * tig;
                    *(float2*)(Y + (size_t)gr * DV + col) = st[nj];
                }
                if (tig == 0)
                    atomicAdd(avec + gr, dp + (add_ab ? abv : 0.0f));
            }
        }
    }
}

// ============================================================
// Zero the attention-scalar accumulators (replay-safe)
// ============================================================
__global__ void zero_avec_kernel(float* a, float* b, float* c, float* d)
{
    const int i = blockIdx.x * blockDim.x + threadIdx.x;
    if (i < N0V) { a[i] = 0.f; b[i] = 0.f; }
    if (i < N1V) c[i] = 0.f;
    if (i < N2V) d[i] = 0.f;
}

// ============================================================
// Edge aggregation: out[r,:] += sigmoid(ai[r]+aj[c]) * xj[c,:]
// One warp per edge; red.global.add.v4.f32.
// ============================================================
__device__ __forceinline__ void red_add_v4(float* p, float4 v)
{
    asm volatile("red.global.add.v4.f32 [%0], {%1, %2, %3, %4};"
                 :: "l"(p), "f"(v.x), "f"(v.y), "f"(v.z), "f"(v.w)
                 : "memory");
}

__global__ void edge_kernel(const int* __restrict__ rows,
                            const int* __restrict__ cols,
                            const float* __restrict__ ai,
                            const float* __restrict__ aj,
                            const float* __restrict__ xj,
                            float* __restrict__ out,
                            int E)
{
    const int e    = (int)((blockIdx.x * (unsigned)blockDim.x + threadIdx.x) >> 5);
    const int lane = threadIdx.x & 31;
    if (e >= E) return;

    const int r = __ldg(rows + e);
    const int c = __ldg(cols + e);
    const float s   = __ldg(ai + r) + __ldg(aj + c);
    const float att = 1.0f / (1.0f + __expf(-s));

    const float4* src = (const float4*)(xj + (size_t)c * DV);
    float* dst = out + (size_t)r * DV;

    float4 v0 = __ldg(src + lane);
    float4 v1 = __ldg(src + 32 + lane);
    v0.x *= att; v0.y *= att; v0.z *= att; v0.w *= att;
    v1.x *= att; v1.y *= att; v1.z *= att; v1.w *= att;

    red_add_v4(dst + lane * 4, v0);
    red_add_v4(dst + 128 + lane * 4, v1);
}

// ============================================================
// Launch
// ============================================================
extern "C" void kernel_launch(void* const* d_in, const int* in_sizes, int n_in,
                              void* d_out, int out_size)
{
    const float* x0    = (const float*)d_in[0];
    const float* x1    = (const float*)d_in[1];
    const float* x2    = (const float*)d_in[2];
    const int*   rows0 = (const int*)d_in[3];
    const int*   cols0 = (const int*)d_in[4];
    const int*   rows1 = (const int*)d_in[5];
    const int*   cols1 = (const int*)d_in[6];
    const int*   rows2 = (const int*)d_in[7];
    const int*   cols2 = (const int*)d_in[8];
    const float* W1 = (const float*)d_in[9];
    const float* b1 = (const float*)d_in[10];
    const float* W2 = (const float*)d_in[11];
    const float* b2 = (const float*)d_in[12];
    const float* W3 = (const float*)d_in[13];
    const float* b3 = (const float*)d_in[14];
    const float* W4 = (const float*)d_in[15];
    const float* b4 = (const float*)d_in[16];
    const float* a1w = (const float*)d_in[17];
    const float* a1b = (const float*)d_in[18];
    const float* a2w = (const float*)d_in[19];
    const float* a2b = (const float*)d_in[20];

    const int E0 = in_sizes[3];
    const int E1 = in_sizes[5];
    const int E2 = in_sizes[7];

    float* out = (float*)d_out;

    float *xj0, *xj1, *xj2, *ai0, *aj0, *aj1, *aj2;
    cudaGetSymbolAddress((void**)&xj0, g_xj0);
    cudaGetSymbolAddress((void**)&xj1, g_xj1);
    cudaGetSymbolAddress((void**)&xj2, g_xj2);
    cudaGetSymbolAddress((void**)&ai0, g_ai0);
    cudaGetSymbolAddress((void**)&aj0, g_aj0);
    cudaGetSymbolAddress((void**)&aj1, g_aj1);
    cudaGetSymbolAddress((void**)&aj2, g_aj2);

    static bool attr_set = false;
    if (!attr_set) {
        cudaFuncSetAttribute(gemm_tf32_kernel,
                             cudaFuncAttributeMaxDynamicSharedMemorySize, SMEM_BYTES);
        attr_set = true;
    }

    // 0) zero attention accumulators (graph-replay safe)
    zero_avec_kernel<<<(N1V + 255) / 256, 256>>>(ai0, aj0, aj1, aj2);

    // 1) GEMMs (tensor core tf32, fused attention dot).
    //    Order so xj0/out are freshest in L2 when edge0 runs.
    gemm_tf32_kernel<<<(N1V + BM - 1) / BM, 512, SMEM_BYTES>>>(x1, W3, b3, a2w, a2b, xj1, aj1, N1V);
    gemm_tf32_kernel<<<(N2V + BM - 1) / BM, 512, SMEM_BYTES>>>(x2, W4, b4, a2w, a2b, xj2, aj2, N2V);
    gemm_tf32_kernel<<<(N0V + BM - 1) / BM, 512, SMEM_BYTES>>>(x0, W1, b1, a1w, a1b, out, ai0, N0V);
    gemm_tf32_kernel<<<(N0V + BM - 1) / BM, 512, SMEM_BYTES>>>(x0, W2, b2, a2w, a2b, xj0, aj0, N0V);

    // 2) edge aggregations (atomic vector adds into d_out); edge0 first (hot L2)
    edge_kernel<<<(int)(((size_t)E0 * 32 + 255) / 256), 256>>>(rows0, cols0, ai0, aj0, xj0, out, E0);
    edge_kernel<<<(int)(((size_t)E1 * 32 + 255) / 256), 256>>>(rows1, cols1, ai0, aj1, xj1, out, E1);
    edge_kernel<<<(int)(((size_t)E2 * 32 + 255) / 256), 256>>>(rows2, cols2, ai0, aj2, xj2, out, E2);
}